// round 1
// baseline (speedup 1.0000x reference)
#include <cuda_runtime.h>
#include <cuda_bf16.h>
#include <math.h>

// Problem constants
#define BATCH 4
#define SEQ   2048
#define HID   1024
#define NH    16
#define HD    64
#define RANK  8
#define LORA_SCALE 2.0f

// Scratch (static device allocations are the sanctioned workaround)
__device__ float g_Weff[3][HID * HID];                       // 12 MB
__device__ float g_QKV[3][BATCH * NH * SEQ * HD];            // 100 MB, [p][b][h][t][d]

// ---------------------------------------------------------------------------
// Kernel 1: fold LoRA into effective weights
//   W_eff[o,i] = W[o,i] + 2 * sum_r B[o,r] * A[r,i]
// ---------------------------------------------------------------------------
__global__ void weff_kernel(const float* __restrict__ Wq, const float* __restrict__ Aq, const float* __restrict__ Bq,
                            const float* __restrict__ Wk, const float* __restrict__ Ak, const float* __restrict__ Bk,
                            const float* __restrict__ Wv, const float* __restrict__ Av, const float* __restrict__ Bv)
{
    int p = blockIdx.y;
    const float* W  = (p == 0) ? Wq : (p == 1) ? Wk : Wv;
    const float* A  = (p == 0) ? Aq : (p == 1) ? Ak : Av;
    const float* Bm = (p == 0) ? Bq : (p == 1) ? Bk : Bv;

    int idx = blockIdx.x * blockDim.x + threadIdx.x;   // over HID*HID
    int o = idx >> 10;
    int i = idx & 1023;
    float acc = 0.f;
#pragma unroll
    for (int r = 0; r < RANK; r++)
        acc += Bm[o * RANK + r] * A[(r << 10) + i];
    g_Weff[p][idx] = W[idx] + LORA_SCALE * acc;
}

// ---------------------------------------------------------------------------
// Kernel 2: QKV projection GEMM.
//   C[m, o] = sum_i X[m, i] * W_eff[o, i] + bias[o]
//   m = b*SEQ + t  (M = 8192), o = h*HD + d (N = 1024), K = 1024
//   Output scattered directly into [b][h][t][d] layout for the attention pass.
// Tiles: BM=BN=128, BK=16, 256 threads, 8x8 register tile per thread.
// ---------------------------------------------------------------------------
#define GBM 128
#define GBN 128
#define GBK 16

__global__ __launch_bounds__(256)
void qkv_gemm(const float* __restrict__ X,
              const float* __restrict__ biasq,
              const float* __restrict__ biask,
              const float* __restrict__ biasv)
{
    int p = blockIdx.z;
    const float* bias = (p == 0) ? biasq : (p == 1) ? biask : biasv;
    const float* Wf = g_Weff[p];
    float* out = g_QKV[p];

    __shared__ float Xs[GBK][GBM + 4];
    __shared__ float Ws[GBK][GBN + 4];

    int tid = threadIdx.x;
    int tx = tid & 15;          // n-dim, 16 threads
    int ty = tid >> 4;          // m-dim, 16 threads
    int m0 = blockIdx.y * GBM;
    int n0 = blockIdx.x * GBN;

    float acc[8][8];
#pragma unroll
    for (int i = 0; i < 8; i++)
#pragma unroll
        for (int j = 0; j < 8; j++) acc[i][j] = 0.f;

    for (int k0 = 0; k0 < HID; k0 += GBK) {
        // Load X tile: 128 rows x 16 k  (512 float4 slots, 256 threads, 2 iters)
#pragma unroll
        for (int it = 0; it < 2; it++) {
            int lin = it * 256 + tid;          // 0..511
            int r  = lin >> 2;                 // 0..127
            int kc = (lin & 3) << 2;           // 0,4,8,12
            float4 v = *(const float4*)&X[(size_t)(m0 + r) * HID + k0 + kc];
            Xs[kc + 0][r] = v.x; Xs[kc + 1][r] = v.y;
            Xs[kc + 2][r] = v.z; Xs[kc + 3][r] = v.w;
        }
        // Load W tile: 128 o-rows x 16 i
#pragma unroll
        for (int it = 0; it < 2; it++) {
            int lin = it * 256 + tid;
            int r  = lin >> 2;
            int kc = (lin & 3) << 2;
            float4 w = *(const float4*)&Wf[(size_t)(n0 + r) * HID + k0 + kc];
            Ws[kc + 0][r] = w.x; Ws[kc + 1][r] = w.y;
            Ws[kc + 2][r] = w.z; Ws[kc + 3][r] = w.w;
        }
        __syncthreads();

#pragma unroll
        for (int k = 0; k < GBK; k++) {
            float4 a0 = *(const float4*)&Xs[k][ty * 8];
            float4 a1 = *(const float4*)&Xs[k][ty * 8 + 4];
            float4 b0 = *(const float4*)&Ws[k][tx * 8];
            float4 b1 = *(const float4*)&Ws[k][tx * 8 + 4];
            float a[8] = {a0.x, a0.y, a0.z, a0.w, a1.x, a1.y, a1.z, a1.w};
            float w[8] = {b0.x, b0.y, b0.z, b0.w, b1.x, b1.y, b1.z, b1.w};
#pragma unroll
            for (int i = 0; i < 8; i++)
#pragma unroll
                for (int j = 0; j < 8; j++)
                    acc[i][j] += a[i] * w[j];
        }
        __syncthreads();
    }

    // Epilogue: add bias, scatter to [b][h][t][d]
    int nb = n0 + tx * 8;        // first of 8 contiguous o's; stays within one head
    int h  = nb >> 6;
    int d0 = nb & 63;
    float bi[8];
#pragma unroll
    for (int j = 0; j < 8; j++) bi[j] = bias[nb + j];

#pragma unroll
    for (int i = 0; i < 8; i++) {
        int m = m0 + ty * 8 + i;
        int b = m >> 11;         // /SEQ
        int t = m & 2047;
        float* op = out + ((size_t)((b * NH + h) * SEQ + t)) * HD + d0;
        float4 r0 = make_float4(acc[i][0] + bi[0], acc[i][1] + bi[1],
                                acc[i][2] + bi[2], acc[i][3] + bi[3]);
        float4 r1 = make_float4(acc[i][4] + bi[4], acc[i][5] + bi[5],
                                acc[i][6] + bi[6], acc[i][7] + bi[7]);
        *(float4*)op       = r0;
        *(float4*)(op + 4) = r1;
    }
}

// ---------------------------------------------------------------------------
// Kernel 3: causal flash attention, fp32.
//   grid = (qb=32, bh=64), block = 128 threads.
//   BM = BN = 64. Per thread: 4 query rows x 8 cols (keys in S phase,
//   head-dims in PV phase). Row-group = 8 lanes -> width-8 shfl reductions.
//   Smem: Qs, KPs (K tile then P tile), Vs  -- each 64 x 68 floats + mask row.
// ---------------------------------------------------------------------------
#define ATTN_PAD 68
#define ATTN_SMEM_FLOATS (3 * 64 * ATTN_PAD + 64)
#define ATTN_SMEM_BYTES  (ATTN_SMEM_FLOATS * 4)

__device__ __forceinline__ float grpmax8(float v) {
    v = fmaxf(v, __shfl_xor_sync(0xffffffffu, v, 1, 8));
    v = fmaxf(v, __shfl_xor_sync(0xffffffffu, v, 2, 8));
    v = fmaxf(v, __shfl_xor_sync(0xffffffffu, v, 4, 8));
    return v;
}
__device__ __forceinline__ float grpsum8(float v) {
    v += __shfl_xor_sync(0xffffffffu, v, 1, 8);
    v += __shfl_xor_sync(0xffffffffu, v, 2, 8);
    v += __shfl_xor_sync(0xffffffffu, v, 4, 8);
    return v;
}

__global__ __launch_bounds__(128)
void attn_kernel(const float* __restrict__ amask, float* __restrict__ out)
{
    extern __shared__ float smem[];
    float (*Qs)[ATTN_PAD]  = (float(*)[ATTN_PAD])smem;
    float (*KPs)[ATTN_PAD] = (float(*)[ATTN_PAD])(smem + 64 * ATTN_PAD);
    float (*Vs)[ATTN_PAD]  = (float(*)[ATTN_PAD])(smem + 2 * 64 * ATTN_PAD);
    float* maskS           = smem + 3 * 64 * ATTN_PAD;

    int qb = blockIdx.x;         // query block, 32 total
    int bh = blockIdx.y;         // (b*NH + h), 64 total
    int b  = bh >> 4;
    int h  = bh & 15;

    const float* Q = g_QKV[0] + (size_t)bh * SEQ * HD;
    const float* K = g_QKV[1] + (size_t)bh * SEQ * HD;
    const float* V = g_QKV[2] + (size_t)bh * SEQ * HD;

    int tid = threadIdx.x;       // 128
    int tx  = tid & 7;           // 8 threads per row-group
    int g   = tid >> 3;          // 16 row-groups
    int r0  = g * 4;             // 4 rows per thread
    int c0  = tx * 8;            // 8 cols per thread
    int q0  = qb * 64;

    // Load Q tile (64 x 64), padded stride
#pragma unroll
    for (int it = 0; it < 8; it++) {
        int lin = it * 128 + tid;          // 1024 float4 slots
        int r  = lin >> 4;
        int d4 = (lin & 15) << 2;
        *(float4*)&Qs[r][d4] = *(const float4*)&Q[(size_t)(q0 + r) * HD + d4];
    }

    float m_i[4], l_i[4], o[4][8];
#pragma unroll
    for (int i = 0; i < 4; i++) {
        m_i[i] = -INFINITY; l_i[i] = 0.f;
#pragma unroll
        for (int j = 0; j < 8; j++) o[i][j] = 0.f;
    }
    __syncthreads();

    for (int kb = 0; kb <= qb; kb++) {
        int k0 = kb * 64;
        // Load K and V tiles
#pragma unroll
        for (int it = 0; it < 8; it++) {
            int lin = it * 128 + tid;
            int r  = lin >> 4;
            int d4 = (lin & 15) << 2;
            *(float4*)&KPs[r][d4] = *(const float4*)&K[(size_t)(k0 + r) * HD + d4];
            *(float4*)&Vs[r][d4]  = *(const float4*)&V[(size_t)(k0 + r) * HD + d4];
        }
        if (tid < 64) maskS[tid] = amask[b * SEQ + k0 + tid];
        __syncthreads();

        // S = Q K^T for my 4x8 sub-tile
        float s[4][8];
#pragma unroll
        for (int i = 0; i < 4; i++)
#pragma unroll
            for (int j = 0; j < 8; j++) s[i][j] = 0.f;

#pragma unroll
        for (int d = 0; d < HD; d += 4) {
            float4 qv[4];
#pragma unroll
            for (int i = 0; i < 4; i++) qv[i] = *(const float4*)&Qs[r0 + i][d];
#pragma unroll
            for (int j = 0; j < 8; j++) {
                float4 kv = *(const float4*)&KPs[c0 + j][d];
#pragma unroll
                for (int i = 0; i < 4; i++) {
                    s[i][j] += qv[i].x * kv.x + qv[i].y * kv.y
                             + qv[i].z * kv.z + qv[i].w * kv.w;
                }
            }
        }

        // Scale + causal mask + attention mask, then online softmax
        bool diag = (kb == qb);
#pragma unroll
        for (int i = 0; i < 4; i++) {
            float rmax = -INFINITY;
#pragma unroll
            for (int j = 0; j < 8; j++) {
                float v = s[i][j] * 0.125f + maskS[c0 + j];
                if (diag && (c0 + j > r0 + i)) v = -INFINITY;
                s[i][j] = v;
                rmax = fmaxf(rmax, v);
            }
            rmax = grpmax8(rmax);
            float mn = fmaxf(m_i[i], rmax);
            float alpha = __expf(m_i[i] - mn);
            float psum = 0.f;
#pragma unroll
            for (int j = 0; j < 8; j++) {
                float pp = __expf(s[i][j] - mn);
                s[i][j] = pp;
                psum += pp;
            }
            psum = grpsum8(psum);
            l_i[i] = l_i[i] * alpha + psum;
            m_i[i] = mn;
#pragma unroll
            for (int j = 0; j < 8; j++) o[i][j] *= alpha;
        }

        __syncthreads();   // everyone done reading K from KPs
        // Store P into KPs (reuse K buffer)
#pragma unroll
        for (int i = 0; i < 4; i++) {
            *(float4*)&KPs[r0 + i][c0]     = make_float4(s[i][0], s[i][1], s[i][2], s[i][3]);
            *(float4*)&KPs[r0 + i][c0 + 4] = make_float4(s[i][4], s[i][5], s[i][6], s[i][7]);
        }
        __syncthreads();

        // O += P V  (my 4 rows x 8 head-dim cols)
#pragma unroll
        for (int k = 0; k < 64; k += 4) {
            float4 pv[4];
#pragma unroll
            for (int i = 0; i < 4; i++) pv[i] = *(const float4*)&KPs[r0 + i][k];
#pragma unroll
            for (int kk = 0; kk < 4; kk++) {
                float4 v0 = *(const float4*)&Vs[k + kk][c0];
                float4 v1 = *(const float4*)&Vs[k + kk][c0 + 4];
#pragma unroll
                for (int i = 0; i < 4; i++) {
                    float p = (kk == 0) ? pv[i].x : (kk == 1) ? pv[i].y
                            : (kk == 2) ? pv[i].z : pv[i].w;
                    o[i][0] += p * v0.x; o[i][1] += p * v0.y;
                    o[i][2] += p * v0.z; o[i][3] += p * v0.w;
                    o[i][4] += p * v1.x; o[i][5] += p * v1.y;
                    o[i][6] += p * v1.z; o[i][7] += p * v1.w;
                }
            }
        }
        __syncthreads();   // before next iteration overwrites KPs / Vs
    }

    // Final normalize + write to d_out as [b][t][h*HD + d]
#pragma unroll
    for (int i = 0; i < 4; i++) {
        float inv = 1.f / l_i[i];
        int q = q0 + r0 + i;
        float* op = out + ((size_t)(b * SEQ + q)) * HID + h * HD + c0;
        float4 w0 = make_float4(o[i][0] * inv, o[i][1] * inv, o[i][2] * inv, o[i][3] * inv);
        float4 w1 = make_float4(o[i][4] * inv, o[i][5] * inv, o[i][6] * inv, o[i][7] * inv);
        *(float4*)op       = w0;
        *(float4*)(op + 4) = w1;
    }
}

// ---------------------------------------------------------------------------
// Launch
// ---------------------------------------------------------------------------
extern "C" void kernel_launch(void* const* d_in, const int* in_sizes, int n_in,
                              void* d_out, int out_size)
{
    (void)in_sizes; (void)n_in; (void)out_size;

    const float* X    = (const float*)d_in[0];
    const float* amsk = (const float*)d_in[1];
    const float* Wq = (const float*)d_in[2];
    const float* bq = (const float*)d_in[3];
    const float* Aq = (const float*)d_in[4];
    const float* Bq = (const float*)d_in[5];
    const float* Wk = (const float*)d_in[6];
    const float* bk = (const float*)d_in[7];
    const float* Ak = (const float*)d_in[8];
    const float* Bk = (const float*)d_in[9];
    const float* Wv = (const float*)d_in[10];
    const float* bv = (const float*)d_in[11];
    const float* Av = (const float*)d_in[12];
    const float* Bv = (const float*)d_in[13];

    // 1) Fold LoRA into W_eff
    weff_kernel<<<dim3(HID * HID / 256, 3), 256>>>(Wq, Aq, Bq, Wk, Ak, Bk, Wv, Av, Bv);

    // 2) QKV projections -> g_QKV in [b][h][t][d]
    qkv_gemm<<<dim3(HID / GBN, (BATCH * SEQ) / GBM, 3), 256>>>(X, bq, bk, bv);

    // 3) Causal flash attention -> d_out
    cudaFuncSetAttribute(attn_kernel, cudaFuncAttributeMaxDynamicSharedMemorySize, ATTN_SMEM_BYTES);
    attn_kernel<<<dim3(SEQ / 64, BATCH * NH), 128, ATTN_SMEM_BYTES>>>(amsk, (float*)d_out);
}

// round 4
// speedup vs baseline: 1.1776x; 1.1776x over previous
#include <cuda_runtime.h>
#include <cuda_bf16.h>
#include <math.h>
#include <stdint.h>

// Problem constants
#define BATCH 4
#define SEQ   2048
#define HID   1024
#define NH    16
#define HD    64
#define RANK  8
#define LORA_SCALE 2.0f

// ---------------------------------------------------------------------------
// Device scratch
// ---------------------------------------------------------------------------
__device__ __nv_bfloat16 g_Xhi[BATCH * SEQ * HID];     // 16 MB
__device__ __nv_bfloat16 g_Xlo[BATCH * SEQ * HID];     // 16 MB
__device__ __nv_bfloat16 g_Whi[3][HID * HID];          // 6 MB
__device__ __nv_bfloat16 g_Wlo[3][HID * HID];          // 6 MB
__device__ float g_QKV[3][BATCH * NH * SEQ * HD];      // 100 MB, [p][b][h][t][d]

// ---------------------------------------------------------------------------
// Helpers
// ---------------------------------------------------------------------------
__device__ __forceinline__ uint32_t smem_u32(const void* p) {
    uint32_t a;
    asm("{ .reg .u64 t; cvta.to.shared.u64 t, %1; cvt.u32.u64 %0, t; }" : "=r"(a) : "l"(p));
    return a;
}
__device__ __forceinline__ void cpa16(uint32_t s, const void* g) {
    asm volatile("cp.async.cg.shared.global [%0], [%1], 16;" :: "r"(s), "l"(g) : "memory");
}
__device__ __forceinline__ void cp_commit() {
    asm volatile("cp.async.commit_group;" ::: "memory");
}
template <int N>
__device__ __forceinline__ void cp_wait() {
    asm volatile("cp.async.wait_group %0;" :: "n"(N) : "memory");
}
__device__ __forceinline__ void ldm4(uint32_t* r, uint32_t addr) {
    asm volatile("ldmatrix.sync.aligned.m8n8.x4.shared.b16 {%0,%1,%2,%3}, [%4];"
                 : "=r"(r[0]), "=r"(r[1]), "=r"(r[2]), "=r"(r[3]) : "r"(addr));
}
__device__ __forceinline__ void mma_bf16(float* c, const uint32_t* a, const uint32_t* b) {
    asm volatile(
        "mma.sync.aligned.m16n8k16.row.col.f32.bf16.bf16.f32 "
        "{%0,%1,%2,%3}, {%4,%5,%6,%7}, {%8,%9}, {%0,%1,%2,%3};"
        : "+f"(c[0]), "+f"(c[1]), "+f"(c[2]), "+f"(c[3])
        : "r"(a[0]), "r"(a[1]), "r"(a[2]), "r"(a[3]), "r"(b[0]), "r"(b[1]));
}

// ---------------------------------------------------------------------------
// Kernel 1a: split X into bf16 hi/lo
// ---------------------------------------------------------------------------
__global__ void xsplit_kernel(const float* __restrict__ X)
{
    int i8 = (blockIdx.x * blockDim.x + threadIdx.x) * 8;
    float4 a = *(const float4*)(X + i8);
    float4 b = *(const float4*)(X + i8 + 4);
    float xs[8] = {a.x, a.y, a.z, a.w, b.x, b.y, b.z, b.w};
    union { __nv_bfloat16 h[8]; uint4 v; } uh, ul;
#pragma unroll
    for (int j = 0; j < 8; j++) {
        __nv_bfloat16 hi = __float2bfloat16(xs[j]);
        uh.h[j] = hi;
        ul.h[j] = __float2bfloat16(xs[j] - __bfloat162float(hi));
    }
    *(uint4*)(g_Xhi + i8) = uh.v;
    *(uint4*)(g_Xlo + i8) = ul.v;
}

// ---------------------------------------------------------------------------
// Kernel 1b: fold LoRA into W_eff and split into bf16 hi/lo
// ---------------------------------------------------------------------------
__global__ void weff_kernel(const float* __restrict__ Wq, const float* __restrict__ Aq, const float* __restrict__ Bq,
                            const float* __restrict__ Wk, const float* __restrict__ Ak, const float* __restrict__ Bk,
                            const float* __restrict__ Wv, const float* __restrict__ Av, const float* __restrict__ Bv)
{
    int p = blockIdx.y;
    const float* W  = (p == 0) ? Wq : (p == 1) ? Wk : Wv;
    const float* A  = (p == 0) ? Aq : (p == 1) ? Ak : Av;
    const float* Bm = (p == 0) ? Bq : (p == 1) ? Bk : Bv;

    int i4 = (blockIdx.x * blockDim.x + threadIdx.x) * 4;
    int o = i4 >> 10;
    int i = i4 & 1023;
    float4 w = *(const float4*)&W[i4];
    float br[RANK];
#pragma unroll
    for (int r = 0; r < RANK; r++) br[r] = Bm[o * RANK + r];
    float vals[4] = {w.x, w.y, w.z, w.w};
#pragma unroll
    for (int j = 0; j < 4; j++) {
        float acc = 0.f;
#pragma unroll
        for (int r = 0; r < RANK; r++) acc += br[r] * A[(r << 10) + i + j];
        vals[j] += LORA_SCALE * acc;
    }
    union { __nv_bfloat16 h[4]; uint2 v; } uh, ul;
#pragma unroll
    for (int j = 0; j < 4; j++) {
        __nv_bfloat16 hi = __float2bfloat16(vals[j]);
        uh.h[j] = hi;
        ul.h[j] = __float2bfloat16(vals[j] - __bfloat162float(hi));
    }
    *(uint2*)(g_Whi[p] + i4) = uh.v;
    *(uint2*)(g_Wlo[p] + i4) = ul.v;
}

// ---------------------------------------------------------------------------
// Kernel 2: QKV projection GEMM via mma.sync (bf16 hi/lo, fp32 accum)
//   C[m,o] = sum_i X[m,i] * W[o,i] + bias[o]   (M=8192, N=1024, K=1024)
//   CTA 128x128, warps 2x4 (warp tile 64x32), K-chunk 32, cp.async dbl buffer.
//   SMEM tile layout: [128 rows][40 bf16] (80 B stride, conflict-free ldmatrix)
// ---------------------------------------------------------------------------
#define PADK 40
#define TILE_B (128 * PADK * 2)        // 10240 bytes per tile
#define STG_B  (4 * TILE_B)            // 40960 bytes per stage
#define GEMM_SMEM (2 * STG_B)          // 81920 bytes
#define NCHUNK 32                      // 1024 / 32

__global__ __launch_bounds__(256, 1)
void qkv_gemm_mma(const float* __restrict__ biasq,
                  const float* __restrict__ biask,
                  const float* __restrict__ biasv)
{
    extern __shared__ char smem[];
    uint32_t sbase = smem_u32(smem);

    int tid  = threadIdx.x;
    int lane = tid & 31;
    int wid  = tid >> 5;
    int warp_m = wid >> 2;            // 0..1  (64-row halves)
    int warp_n = wid & 3;             // 0..3  (32-col quarters)

    int p  = blockIdx.z;
    const float* bias = (p == 0) ? biasq : (p == 1) ? biask : biasv;
    const __nv_bfloat16* Xhi = g_Xhi;
    const __nv_bfloat16* Xlo = g_Xlo;
    const __nv_bfloat16* Whi = g_Whi[p];
    const __nv_bfloat16* Wlo = g_Wlo[p];
    int m0 = blockIdx.y * 128;
    int n0 = blockIdx.x * 128;

    // per-thread copy assignment: rows row0 and row0+64, 16B segment seg0
    int row0 = tid >> 2;
    int seg0 = tid & 3;

    // async copy of one 32-col chunk (4 tiles) into stage st
    auto copy_chunk = [&](int c, int st) {
        int col0 = c * 32 + seg0 * 8;
        uint32_t sb = sbase + st * STG_B + row0 * (PADK * 2) + seg0 * 16;
        const __nv_bfloat16* gx = Xhi + (size_t)(m0 + row0) * HID + col0;
        cpa16(sb,                       gx);
        cpa16(sb + 64 * (PADK * 2),     gx + 64 * HID);
        gx = Xlo + (size_t)(m0 + row0) * HID + col0;
        cpa16(sb + TILE_B,                   gx);
        cpa16(sb + TILE_B + 64 * (PADK * 2), gx + 64 * HID);
        const __nv_bfloat16* gw = Whi + (size_t)(n0 + row0) * HID + col0;
        cpa16(sb + 2 * TILE_B,                   gw);
        cpa16(sb + 2 * TILE_B + 64 * (PADK * 2), gw + 64 * HID);
        gw = Wlo + (size_t)(n0 + row0) * HID + col0;
        cpa16(sb + 3 * TILE_B,                   gw);
        cpa16(sb + 3 * TILE_B + 64 * (PADK * 2), gw + 64 * HID);
    };

    float acc[4][4][4];
#pragma unroll
    for (int mt = 0; mt < 4; mt++)
#pragma unroll
        for (int nt = 0; nt < 4; nt++)
#pragma unroll
            for (int k = 0; k < 4; k++) acc[mt][nt][k] = 0.f;

    // ldmatrix per-lane address components (element offsets within a tile)
    // A (x4 -> 16x16): row = (lane&7) + ((lane>>3)&1)*8  [+ mt*16], col = (lane>>4)*8 [+ ks]
    int a_row = warp_m * 64 + (lane & 7) + ((lane >> 3) & 1) * 8;
    int a_col = (lane >> 4) * 8;
    // B (x4 -> 16 n-rows x 16 k): row = (lane&7) + ((lane>>4)&1)*8 [+ np*16], col = ((lane>>3)&1)*8 [+ ks]
    int b_row = warp_n * 32 + (lane & 7) + ((lane >> 4) & 1) * 8;
    int b_col = ((lane >> 3) & 1) * 8;

    copy_chunk(0, 0);
    cp_commit();

    for (int c = 0; c < NCHUNK; ++c) {
        if (c + 1 < NCHUNK) {
            copy_chunk(c + 1, (c + 1) & 1);
            cp_commit();
            cp_wait<1>();
        } else {
            cp_wait<0>();
        }
        __syncthreads();

        uint32_t xs_hi = sbase + (uint32_t)(c & 1) * STG_B;
        uint32_t xs_lo = xs_hi + TILE_B;
        uint32_t ws_hi = xs_hi + 2 * TILE_B;
        uint32_t ws_lo = xs_hi + 3 * TILE_B;

#pragma unroll
        for (int ks = 0; ks < 32; ks += 16) {
            uint32_t ah[16], al[16], bh[8], bl[8];
#pragma unroll
            for (int mt = 0; mt < 4; mt++) {
                uint32_t off = (uint32_t)(((a_row + mt * 16) * PADK + a_col + ks) * 2);
                ldm4(ah + 4 * mt, xs_hi + off);
                ldm4(al + 4 * mt, xs_lo + off);
            }
#pragma unroll
            for (int np = 0; np < 2; np++) {
                uint32_t off = (uint32_t)(((b_row + np * 16) * PADK + b_col + ks) * 2);
                ldm4(bh + 4 * np, ws_hi + off);
                ldm4(bl + 4 * np, ws_lo + off);
            }
#pragma unroll
            for (int mt = 0; mt < 4; mt++) {
#pragma unroll
                for (int nt = 0; nt < 4; nt++) {
                    const uint32_t* bp_hi = bh + 4 * (nt >> 1) + 2 * (nt & 1);
                    const uint32_t* bp_lo = bl + 4 * (nt >> 1) + 2 * (nt & 1);
                    mma_bf16(acc[mt][nt], ah + 4 * mt, bp_hi);   // hi*hi
                    mma_bf16(acc[mt][nt], ah + 4 * mt, bp_lo);   // hi*lo
                    mma_bf16(acc[mt][nt], al + 4 * mt, bp_hi);   // lo*hi
                }
            }
        }
        __syncthreads();
    }

    // Epilogue: add bias, scatter to g_QKV[p] laid out [b][h][t][d]
    float* out = g_QKV[p];
#pragma unroll
    for (int mt = 0; mt < 4; mt++) {
        int mrow = m0 + warp_m * 64 + mt * 16 + (lane >> 2);
#pragma unroll
        for (int nt = 0; nt < 4; nt++) {
            int o = n0 + warp_n * 32 + nt * 8 + (lane & 3) * 2;
            int h = o >> 6;
            int d = o & 63;
            float b0 = __ldg(&bias[o]);
            float b1 = __ldg(&bias[o + 1]);
#pragma unroll
            for (int half = 0; half < 2; half++) {
                int m = mrow + half * 8;
                int b = m >> 11;
                int t = m & 2047;
                float* op = out + ((size_t)((b * NH + h) * SEQ + t)) * HD + d;
                float2 v = make_float2(acc[mt][nt][half * 2] + b0,
                                       acc[mt][nt][half * 2 + 1] + b1);
                *(float2*)op = v;
            }
        }
    }
}

// ---------------------------------------------------------------------------
// Kernel 3: causal flash attention, fp32 (unchanged from R1 baseline)
// ---------------------------------------------------------------------------
#define ATTN_PAD 68
#define ATTN_SMEM_FLOATS (3 * 64 * ATTN_PAD + 64)
#define ATTN_SMEM_BYTES  (ATTN_SMEM_FLOATS * 4)

__device__ __forceinline__ float grpmax8(float v) {
    v = fmaxf(v, __shfl_xor_sync(0xffffffffu, v, 1, 8));
    v = fmaxf(v, __shfl_xor_sync(0xffffffffu, v, 2, 8));
    v = fmaxf(v, __shfl_xor_sync(0xffffffffu, v, 4, 8));
    return v;
}
__device__ __forceinline__ float grpsum8(float v) {
    v += __shfl_xor_sync(0xffffffffu, v, 1, 8);
    v += __shfl_xor_sync(0xffffffffu, v, 2, 8);
    v += __shfl_xor_sync(0xffffffffu, v, 4, 8);
    return v;
}

__global__ __launch_bounds__(128)
void attn_kernel(const float* __restrict__ amask, float* __restrict__ out)
{
    extern __shared__ float fsm[];
    float (*Qs)[ATTN_PAD]  = (float(*)[ATTN_PAD])fsm;
    float (*KPs)[ATTN_PAD] = (float(*)[ATTN_PAD])(fsm + 64 * ATTN_PAD);
    float (*Vs)[ATTN_PAD]  = (float(*)[ATTN_PAD])(fsm + 2 * 64 * ATTN_PAD);
    float* maskS           = fsm + 3 * 64 * ATTN_PAD;

    int qb = blockIdx.x;
    int bh = blockIdx.y;
    int b  = bh >> 4;
    int h  = bh & 15;

    const float* Q = g_QKV[0] + (size_t)bh * SEQ * HD;
    const float* K = g_QKV[1] + (size_t)bh * SEQ * HD;
    const float* V = g_QKV[2] + (size_t)bh * SEQ * HD;

    int tid = threadIdx.x;
    int tx  = tid & 7;
    int g   = tid >> 3;
    int r0  = g * 4;
    int c0  = tx * 8;
    int q0  = qb * 64;

#pragma unroll
    for (int it = 0; it < 8; it++) {
        int lin = it * 128 + tid;
        int r  = lin >> 4;
        int d4 = (lin & 15) << 2;
        *(float4*)&Qs[r][d4] = *(const float4*)&Q[(size_t)(q0 + r) * HD + d4];
    }

    float m_i[4], l_i[4], o[4][8];
#pragma unroll
    for (int i = 0; i < 4; i++) {
        m_i[i] = -INFINITY; l_i[i] = 0.f;
#pragma unroll
        for (int j = 0; j < 8; j++) o[i][j] = 0.f;
    }
    __syncthreads();

    for (int kb = 0; kb <= qb; kb++) {
        int k0 = kb * 64;
#pragma unroll
        for (int it = 0; it < 8; it++) {
            int lin = it * 128 + tid;
            int r  = lin >> 4;
            int d4 = (lin & 15) << 2;
            *(float4*)&KPs[r][d4] = *(const float4*)&K[(size_t)(k0 + r) * HD + d4];
            *(float4*)&Vs[r][d4]  = *(const float4*)&V[(size_t)(k0 + r) * HD + d4];
        }
        if (tid < 64) maskS[tid] = amask[b * SEQ + k0 + tid];
        __syncthreads();

        float s[4][8];
#pragma unroll
        for (int i = 0; i < 4; i++)
#pragma unroll
            for (int j = 0; j < 8; j++) s[i][j] = 0.f;

#pragma unroll
        for (int d = 0; d < HD; d += 4) {
            float4 qv[4];
#pragma unroll
            for (int i = 0; i < 4; i++) qv[i] = *(const float4*)&Qs[r0 + i][d];
#pragma unroll
            for (int j = 0; j < 8; j++) {
                float4 kv = *(const float4*)&KPs[c0 + j][d];
#pragma unroll
                for (int i = 0; i < 4; i++) {
                    s[i][j] += qv[i].x * kv.x + qv[i].y * kv.y
                             + qv[i].z * kv.z + qv[i].w * kv.w;
                }
            }
        }

        bool diag = (kb == qb);
#pragma unroll
        for (int i = 0; i < 4; i++) {
            float rmax = -INFINITY;
#pragma unroll
            for (int j = 0; j < 8; j++) {
                float v = s[i][j] * 0.125f + maskS[c0 + j];
                if (diag && (c0 + j > r0 + i)) v = -INFINITY;
                s[i][j] = v;
                rmax = fmaxf(rmax, v);
            }
            rmax = grpmax8(rmax);
            float mn = fmaxf(m_i[i], rmax);
            float alpha = __expf(m_i[i] - mn);
            float psum = 0.f;
#pragma unroll
            for (int j = 0; j < 8; j++) {
                float pp = __expf(s[i][j] - mn);
                s[i][j] = pp;
                psum += pp;
            }
            psum = grpsum8(psum);
            l_i[i] = l_i[i] * alpha + psum;
            m_i[i] = mn;
#pragma unroll
            for (int j = 0; j < 8; j++) o[i][j] *= alpha;
        }

        __syncthreads();
#pragma unroll
        for (int i = 0; i < 4; i++) {
            *(float4*)&KPs[r0 + i][c0]     = make_float4(s[i][0], s[i][1], s[i][2], s[i][3]);
            *(float4*)&KPs[r0 + i][c0 + 4] = make_float4(s[i][4], s[i][5], s[i][6], s[i][7]);
        }
        __syncthreads();

#pragma unroll
        for (int k = 0; k < 64; k += 4) {
            float4 pv[4];
#pragma unroll
            for (int i = 0; i < 4; i++) pv[i] = *(const float4*)&KPs[r0 + i][k];
#pragma unroll
            for (int kk = 0; kk < 4; kk++) {
                float4 v0 = *(const float4*)&Vs[k + kk][c0];
                float4 v1 = *(const float4*)&Vs[k + kk][c0 + 4];
#pragma unroll
                for (int i = 0; i < 4; i++) {
                    float pp = (kk == 0) ? pv[i].x : (kk == 1) ? pv[i].y
                             : (kk == 2) ? pv[i].z : pv[i].w;
                    o[i][0] += pp * v0.x; o[i][1] += pp * v0.y;
                    o[i][2] += pp * v0.z; o[i][3] += pp * v0.w;
                    o[i][4] += pp * v1.x; o[i][5] += pp * v1.y;
                    o[i][6] += pp * v1.z; o[i][7] += pp * v1.w;
                }
            }
        }
        __syncthreads();
    }

#pragma unroll
    for (int i = 0; i < 4; i++) {
        float inv = 1.f / l_i[i];
        int q = q0 + r0 + i;
        float* op = out + ((size_t)(b * SEQ + q)) * HID + h * HD + c0;
        float4 w0 = make_float4(o[i][0] * inv, o[i][1] * inv, o[i][2] * inv, o[i][3] * inv);
        float4 w1 = make_float4(o[i][4] * inv, o[i][5] * inv, o[i][6] * inv, o[i][7] * inv);
        *(float4*)op       = w0;
        *(float4*)(op + 4) = w1;
    }
}

// ---------------------------------------------------------------------------
// Launch
// ---------------------------------------------------------------------------
extern "C" void kernel_launch(void* const* d_in, const int* in_sizes, int n_in,
                              void* d_out, int out_size)
{
    (void)in_sizes; (void)n_in; (void)out_size;

    const float* X    = (const float*)d_in[0];
    const float* amsk = (const float*)d_in[1];
    const float* Wq = (const float*)d_in[2];
    const float* bq = (const float*)d_in[3];
    const float* Aq = (const float*)d_in[4];
    const float* Bq = (const float*)d_in[5];
    const float* Wk = (const float*)d_in[6];
    const float* bk = (const float*)d_in[7];
    const float* Ak = (const float*)d_in[8];
    const float* Bk = (const float*)d_in[9];
    const float* Wv = (const float*)d_in[10];
    const float* bv = (const float*)d_in[11];
    const float* Av = (const float*)d_in[12];
    const float* Bv = (const float*)d_in[13];

    // 1) Split X to bf16 hi/lo; fold LoRA into W_eff hi/lo
    xsplit_kernel<<<BATCH * SEQ * HID / (256 * 8), 256>>>(X);
    weff_kernel<<<dim3(HID * HID / 1024, 3), 256>>>(Wq, Aq, Bq, Wk, Ak, Bk, Wv, Av, Bv);

    // 2) QKV projections via mma.sync -> g_QKV in [b][h][t][d]
    cudaFuncSetAttribute(qkv_gemm_mma, cudaFuncAttributeMaxDynamicSharedMemorySize, GEMM_SMEM);
    qkv_gemm_mma<<<dim3(HID / 128, (BATCH * SEQ) / 128, 3), 256, GEMM_SMEM>>>(bq, bk, bv);

    // 3) Causal flash attention -> d_out
    cudaFuncSetAttribute(attn_kernel, cudaFuncAttributeMaxDynamicSharedMemorySize, ATTN_SMEM_BYTES);
    attn_kernel<<<dim3(SEQ / 64, BATCH * NH), 128, ATTN_SMEM_BYTES>>>(amsk, (float*)d_out);
}

// round 6
// speedup vs baseline: 3.9918x; 3.3897x over previous
#include <cuda_runtime.h>
#include <cuda_bf16.h>
#include <math.h>
#include <stdint.h>

// Problem constants
#define BATCH 4
#define SEQ   2048
#define HID   1024
#define NH    16
#define HD    64
#define RANK  8
#define LORA_SCALE 2.0f

// ---------------------------------------------------------------------------
// Device scratch: X and W_eff in bf16 hi/lo; Q/K/V results in bf16 hi/lo
// ---------------------------------------------------------------------------
__device__ __nv_bfloat16 g_Xhi[BATCH * SEQ * HID];
__device__ __nv_bfloat16 g_Xlo[BATCH * SEQ * HID];
__device__ __nv_bfloat16 g_Whi[3][HID * HID];
__device__ __nv_bfloat16 g_Wlo[3][HID * HID];
__device__ __nv_bfloat16 g_Ph[3][BATCH * NH * SEQ * HD];   // [p][b][h][t][d] hi
__device__ __nv_bfloat16 g_Pl[3][BATCH * NH * SEQ * HD];   // lo

// ---------------------------------------------------------------------------
// Helpers
// ---------------------------------------------------------------------------
__device__ __forceinline__ uint32_t smem_u32(const void* p) {
    uint32_t a;
    asm("{ .reg .u64 t; cvta.to.shared.u64 t, %1; cvt.u32.u64 %0, t; }" : "=r"(a) : "l"(p));
    return a;
}
__device__ __forceinline__ void cpa16(uint32_t s, const void* g) {
    asm volatile("cp.async.cg.shared.global [%0], [%1], 16;" :: "r"(s), "l"(g) : "memory");
}
__device__ __forceinline__ void cp_commit() {
    asm volatile("cp.async.commit_group;" ::: "memory");
}
template <int N>
__device__ __forceinline__ void cp_wait() {
    asm volatile("cp.async.wait_group %0;" :: "n"(N) : "memory");
}
__device__ __forceinline__ void ldm4(uint32_t* r, uint32_t addr) {
    asm volatile("ldmatrix.sync.aligned.m8n8.x4.shared.b16 {%0,%1,%2,%3}, [%4];"
                 : "=r"(r[0]), "=r"(r[1]), "=r"(r[2]), "=r"(r[3]) : "r"(addr));
}
__device__ __forceinline__ void ldm4t(uint32_t* r, uint32_t addr) {
    asm volatile("ldmatrix.sync.aligned.m8n8.x4.trans.shared.b16 {%0,%1,%2,%3}, [%4];"
                 : "=r"(r[0]), "=r"(r[1]), "=r"(r[2]), "=r"(r[3]) : "r"(addr));
}
__device__ __forceinline__ void mma_bf16(float* c, const uint32_t* a, const uint32_t* b) {
    asm volatile(
        "mma.sync.aligned.m16n8k16.row.col.f32.bf16.bf16.f32 "
        "{%0,%1,%2,%3}, {%4,%5,%6,%7}, {%8,%9}, {%0,%1,%2,%3};"
        : "+f"(c[0]), "+f"(c[1]), "+f"(c[2]), "+f"(c[3])
        : "r"(a[0]), "r"(a[1]), "r"(a[2]), "r"(a[3]), "r"(b[0]), "r"(b[1]));
}
__device__ __forceinline__ uint32_t packbf2(float x, float y) {
    __nv_bfloat162 t = __floats2bfloat162_rn(x, y);
    return *(uint32_t*)&t;
}

// ---------------------------------------------------------------------------
// Kernel 1a: split X into bf16 hi/lo
// ---------------------------------------------------------------------------
__global__ void xsplit_kernel(const float* __restrict__ X)
{
    int i8 = (blockIdx.x * blockDim.x + threadIdx.x) * 8;
    float4 a = *(const float4*)(X + i8);
    float4 b = *(const float4*)(X + i8 + 4);
    float xs[8] = {a.x, a.y, a.z, a.w, b.x, b.y, b.z, b.w};
    union { __nv_bfloat16 h[8]; uint4 v; } uh, ul;
#pragma unroll
    for (int j = 0; j < 8; j++) {
        __nv_bfloat16 hi = __float2bfloat16(xs[j]);
        uh.h[j] = hi;
        ul.h[j] = __float2bfloat16(xs[j] - __bfloat162float(hi));
    }
    *(uint4*)(g_Xhi + i8) = uh.v;
    *(uint4*)(g_Xlo + i8) = ul.v;
}

// ---------------------------------------------------------------------------
// Kernel 1b: fold LoRA into W_eff and split into bf16 hi/lo
// ---------------------------------------------------------------------------
__global__ void weff_kernel(const float* __restrict__ Wq, const float* __restrict__ Aq, const float* __restrict__ Bq,
                            const float* __restrict__ Wk, const float* __restrict__ Ak, const float* __restrict__ Bk,
                            const float* __restrict__ Wv, const float* __restrict__ Av, const float* __restrict__ Bv)
{
    int p = blockIdx.y;
    const float* W  = (p == 0) ? Wq : (p == 1) ? Wk : Wv;
    const float* A  = (p == 0) ? Aq : (p == 1) ? Ak : Av;
    const float* Bm = (p == 0) ? Bq : (p == 1) ? Bk : Bv;

    int i4 = (blockIdx.x * blockDim.x + threadIdx.x) * 4;
    int o = i4 >> 10;
    int i = i4 & 1023;
    float4 w = *(const float4*)&W[i4];
    float br[RANK];
#pragma unroll
    for (int r = 0; r < RANK; r++) br[r] = Bm[o * RANK + r];
    float vals[4] = {w.x, w.y, w.z, w.w};
#pragma unroll
    for (int j = 0; j < 4; j++) {
        float acc = 0.f;
#pragma unroll
        for (int r = 0; r < RANK; r++) acc += br[r] * A[(r << 10) + i + j];
        vals[j] += LORA_SCALE * acc;
    }
    union { __nv_bfloat16 h[4]; uint2 v; } uh, ul;
#pragma unroll
    for (int j = 0; j < 4; j++) {
        __nv_bfloat16 hi = __float2bfloat16(vals[j]);
        uh.h[j] = hi;
        ul.h[j] = __float2bfloat16(vals[j] - __bfloat162float(hi));
    }
    *(uint2*)(g_Whi[p] + i4) = uh.v;
    *(uint2*)(g_Wlo[p] + i4) = ul.v;
}

// ---------------------------------------------------------------------------
// Kernel 2: QKV projection GEMM via mma.sync (bf16 hi/lo, fp32 accum)
//   Epilogue: add bias, re-split to bf16 hi/lo, scatter to [b][h][t][d]
// ---------------------------------------------------------------------------
#define PADK 40
#define TILE_B (128 * PADK * 2)
#define STG_B  (4 * TILE_B)
#define GEMM_SMEM (2 * STG_B)
#define NCHUNK 32

__global__ __launch_bounds__(256, 1)
void qkv_gemm_mma(const float* __restrict__ biasq,
                  const float* __restrict__ biask,
                  const float* __restrict__ biasv)
{
    extern __shared__ char smem[];
    uint32_t sbase = smem_u32(smem);

    int tid  = threadIdx.x;
    int lane = tid & 31;
    int wid  = tid >> 5;
    int warp_m = wid >> 2;
    int warp_n = wid & 3;

    int p  = blockIdx.z;
    const float* bias = (p == 0) ? biasq : (p == 1) ? biask : biasv;
    const __nv_bfloat16* Xhi = g_Xhi;
    const __nv_bfloat16* Xlo = g_Xlo;
    const __nv_bfloat16* Whi = g_Whi[p];
    const __nv_bfloat16* Wlo = g_Wlo[p];
    int m0 = blockIdx.y * 128;
    int n0 = blockIdx.x * 128;

    int row0 = tid >> 2;
    int seg0 = tid & 3;

    auto copy_chunk = [&](int c, int st) {
        int col0 = c * 32 + seg0 * 8;
        uint32_t sb = sbase + st * STG_B + row0 * (PADK * 2) + seg0 * 16;
        const __nv_bfloat16* gx = Xhi + (size_t)(m0 + row0) * HID + col0;
        cpa16(sb,                       gx);
        cpa16(sb + 64 * (PADK * 2),     gx + 64 * HID);
        gx = Xlo + (size_t)(m0 + row0) * HID + col0;
        cpa16(sb + TILE_B,                   gx);
        cpa16(sb + TILE_B + 64 * (PADK * 2), gx + 64 * HID);
        const __nv_bfloat16* gw = Whi + (size_t)(n0 + row0) * HID + col0;
        cpa16(sb + 2 * TILE_B,                   gw);
        cpa16(sb + 2 * TILE_B + 64 * (PADK * 2), gw + 64 * HID);
        gw = Wlo + (size_t)(n0 + row0) * HID + col0;
        cpa16(sb + 3 * TILE_B,                   gw);
        cpa16(sb + 3 * TILE_B + 64 * (PADK * 2), gw + 64 * HID);
    };

    float acc[4][4][4];
#pragma unroll
    for (int mt = 0; mt < 4; mt++)
#pragma unroll
        for (int nt = 0; nt < 4; nt++)
#pragma unroll
            for (int k = 0; k < 4; k++) acc[mt][nt][k] = 0.f;

    int a_row = warp_m * 64 + (lane & 7) + ((lane >> 3) & 1) * 8;
    int a_col = (lane >> 4) * 8;
    int b_row = warp_n * 32 + (lane & 7) + ((lane >> 4) & 1) * 8;
    int b_col = ((lane >> 3) & 1) * 8;

    copy_chunk(0, 0);
    cp_commit();

    for (int c = 0; c < NCHUNK; ++c) {
        if (c + 1 < NCHUNK) {
            copy_chunk(c + 1, (c + 1) & 1);
            cp_commit();
            cp_wait<1>();
        } else {
            cp_wait<0>();
        }
        __syncthreads();

        uint32_t xs_hi = sbase + (uint32_t)(c & 1) * STG_B;
        uint32_t xs_lo = xs_hi + TILE_B;
        uint32_t ws_hi = xs_hi + 2 * TILE_B;
        uint32_t ws_lo = xs_hi + 3 * TILE_B;

#pragma unroll
        for (int ks = 0; ks < 32; ks += 16) {
            uint32_t ah[16], al[16], bh[8], bl[8];
#pragma unroll
            for (int mt = 0; mt < 4; mt++) {
                uint32_t off = (uint32_t)(((a_row + mt * 16) * PADK + a_col + ks) * 2);
                ldm4(ah + 4 * mt, xs_hi + off);
                ldm4(al + 4 * mt, xs_lo + off);
            }
#pragma unroll
            for (int np = 0; np < 2; np++) {
                uint32_t off = (uint32_t)(((b_row + np * 16) * PADK + b_col + ks) * 2);
                ldm4(bh + 4 * np, ws_hi + off);
                ldm4(bl + 4 * np, ws_lo + off);
            }
#pragma unroll
            for (int mt = 0; mt < 4; mt++) {
#pragma unroll
                for (int nt = 0; nt < 4; nt++) {
                    const uint32_t* bp_hi = bh + 4 * (nt >> 1) + 2 * (nt & 1);
                    const uint32_t* bp_lo = bl + 4 * (nt >> 1) + 2 * (nt & 1);
                    mma_bf16(acc[mt][nt], ah + 4 * mt, bp_hi);
                    mma_bf16(acc[mt][nt], ah + 4 * mt, bp_lo);
                    mma_bf16(acc[mt][nt], al + 4 * mt, bp_hi);
                }
            }
        }
        __syncthreads();
    }

    // Epilogue: add bias, split to bf16 hi/lo, scatter to [b][h][t][d]
    __nv_bfloat16* oh = g_Ph[p];
    __nv_bfloat16* ol = g_Pl[p];
#pragma unroll
    for (int mt = 0; mt < 4; mt++) {
        int mrow = m0 + warp_m * 64 + mt * 16 + (lane >> 2);
#pragma unroll
        for (int nt = 0; nt < 4; nt++) {
            int o = n0 + warp_n * 32 + nt * 8 + (lane & 3) * 2;
            int h = o >> 6;
            int d = o & 63;
            float b0 = __ldg(&bias[o]);
            float b1 = __ldg(&bias[o + 1]);
#pragma unroll
            for (int half = 0; half < 2; half++) {
                int m = mrow + half * 8;
                int b = m >> 11;
                int t = m & 2047;
                size_t idx = ((size_t)((b * NH + h) * SEQ + t)) * HD + d;
                float v0 = acc[mt][nt][half * 2] + b0;
                float v1 = acc[mt][nt][half * 2 + 1] + b1;
                __nv_bfloat16 h0 = __float2bfloat16(v0);
                __nv_bfloat16 h1 = __float2bfloat16(v1);
                float l0 = v0 - __bfloat162float(h0);
                float l1 = v1 - __bfloat162float(h1);
                union { __nv_bfloat16 h[2]; uint32_t u; } ph, pl;
                ph.h[0] = h0; ph.h[1] = h1;
                pl.h[0] = __float2bfloat16(l0); pl.h[1] = __float2bfloat16(l1);
                *(uint32_t*)(oh + idx) = ph.u;
                *(uint32_t*)(ol + idx) = pl.u;
            }
        }
    }
}

// ---------------------------------------------------------------------------
// Kernel 3: causal flash attention via mma.sync (bf16 hi/lo, fp32 softmax)
//   Tile 64 q x 64 kv, 4 warps (16 q-rows each), Q frags register-resident,
//   K/V double-buffered via cp.async, P repacked in registers (no smem P).
// ---------------------------------------------------------------------------
#define AP 72                       // padded row length in bf16 elems
#define ROWB (AP * 2)               // 144 bytes
#define TILE_KB (64 * ROWB)         // 9216 bytes
#define STAGE_B (4 * TILE_KB + 256) // Kh,Kl,Vh,Vl + mask row
#define ATTN_SMEM (2 * STAGE_B + 2 * TILE_KB)   // 92672 bytes

__global__ __launch_bounds__(128)
void attn_mma(const float* __restrict__ amask, float* __restrict__ out)
{
    extern __shared__ char sm[];
    uint32_t sb = smem_u32(sm);

    int tid  = threadIdx.x;
    int lane = tid & 31;
    int warp = tid >> 5;

    int qb = blockIdx.x;
    int bh = blockIdx.y;
    int b  = bh >> 4;
    int h  = bh & 15;
    int q0 = qb * 64;

    const __nv_bfloat16* Qh = g_Ph[0] + (size_t)bh * SEQ * HD;
    const __nv_bfloat16* Ql = g_Pl[0] + (size_t)bh * SEQ * HD;
    const __nv_bfloat16* Kh = g_Ph[1] + (size_t)bh * SEQ * HD;
    const __nv_bfloat16* Kl = g_Pl[1] + (size_t)bh * SEQ * HD;
    const __nv_bfloat16* Vh = g_Ph[2] + (size_t)bh * SEQ * HD;
    const __nv_bfloat16* Vl = g_Pl[2] + (size_t)bh * SEQ * HD;

    int crow = tid >> 1;             // 0..63
    int cseg = (tid & 1) * 4;        // 0 or 4 (x4 16B segments)

    // K/V/mask stage copy via cp.async
    auto copy_stage = [&](int kb) {
        int st = kb & 1;
        int k0 = kb * 64;
        uint32_t dst = sb + st * STAGE_B + crow * ROWB + cseg * 16;
        size_t src = (size_t)(k0 + crow) * HD + cseg * 8;
#pragma unroll
        for (int c = 0; c < 4; c++) {
            cpa16(dst + c * 16,               Kh + src + c * 8);
            cpa16(dst + c * 16 + TILE_KB,     Kl + src + c * 8);
            cpa16(dst + c * 16 + 2 * TILE_KB, Vh + src + c * 8);
            cpa16(dst + c * 16 + 3 * TILE_KB, Vl + src + c * 8);
        }
        if (tid < 16)
            cpa16(sb + st * STAGE_B + 4 * TILE_KB + tid * 16,
                  amask + (size_t)b * SEQ + k0 + tid * 4);
    };

    // Load Q tile (hi/lo) into smem with plain 16B loads
    {
        uint32_t qdst = sb + 2 * STAGE_B + crow * ROWB + cseg * 16;
        size_t src = (size_t)(q0 + crow) * HD + cseg * 8;
#pragma unroll
        for (int c = 0; c < 4; c++) {
            *(uint4*)(sm + (qdst - sb) + c * 16)           = *(const uint4*)(Qh + src + c * 8);
            *(uint4*)(sm + (qdst - sb) + c * 16 + TILE_KB) = *(const uint4*)(Ql + src + c * 8);
        }
    }

    copy_stage(0);
    cp_commit();
    __syncthreads();   // Q visible

    // Q fragments, register resident: qh/ql[kstep][4]
    uint32_t qfh[4][4], qfl[4][4];
    {
        int arow = warp * 16 + (lane & 15);
        int acol = (lane >> 4) * 8;
        uint32_t qbase = sb + 2 * STAGE_B + arow * ROWB + acol * 2;
#pragma unroll
        for (int ks = 0; ks < 4; ks++) {
            ldm4(qfh[ks], qbase + ks * 32);
            ldm4(qfl[ks], qbase + TILE_KB + ks * 32);
        }
    }

    float o[8][4];
#pragma unroll
    for (int j = 0; j < 8; j++)
#pragma unroll
        for (int k = 0; k < 4; k++) o[j][k] = 0.f;
    float m0 = -INFINITY, m1 = -INFINITY, l0 = 0.f, l1 = 0.f;

    int row_in = warp * 16 + (lane >> 2);   // 0..63 (and +8)
    int c2 = 2 * (lane & 3);

    int krow = (lane & 7) + ((lane >> 4) & 1) * 8;   // K ldmatrix row within n16 group
    int kcol = ((lane >> 3) & 1) * 8;                // K ldmatrix col within k16
    int vrow = lane & 15;                            // V trans row within k16 group
    int vcol = (lane >> 4) * 8;                      // V trans col within d16

    for (int kb = 0; kb <= qb; kb++) {
        cp_wait<0>();
        __syncthreads();
        if (kb + 1 <= qb) {
            copy_stage(kb + 1);
            cp_commit();
        }

        uint32_t st = sb + (uint32_t)(kb & 1) * STAGE_B;

        // ---- S = Q K^T (3 hi/lo passes) ----
        float s[8][4];
#pragma unroll
        for (int j = 0; j < 8; j++)
#pragma unroll
            for (int k = 0; k < 4; k++) s[j][k] = 0.f;

#pragma unroll
        for (int ks = 0; ks < 4; ks++) {
#pragma unroll
            for (int ng = 0; ng < 4; ng++) {
                uint32_t kh4[4], kl4[4];
                uint32_t kaddr = st + (uint32_t)((16 * ng + krow) * ROWB + (kcol + ks * 16) * 2);
                ldm4(kh4, kaddr);
                ldm4(kl4, kaddr + TILE_KB);
                mma_bf16(s[2 * ng],     qfh[ks], kh4);
                mma_bf16(s[2 * ng],     qfh[ks], kl4);
                mma_bf16(s[2 * ng],     qfl[ks], kh4);
                mma_bf16(s[2 * ng + 1], qfh[ks], kh4 + 2);
                mma_bf16(s[2 * ng + 1], qfh[ks], kl4 + 2);
                mma_bf16(s[2 * ng + 1], qfl[ks], kh4 + 2);
            }
        }

        // ---- softmax (online) ----
        const float* maskrow = (const float*)(sm + (kb & 1) * STAGE_B + 4 * TILE_KB);
        bool diag = (kb == qb);
        float mx0 = -INFINITY, mx1 = -INFINITY;
#pragma unroll
        for (int j = 0; j < 8; j++) {
            int cg = 8 * j + c2;
            float mk0 = maskrow[cg], mk1 = maskrow[cg + 1];
            float v0 = fmaf(s[j][0], 0.125f, mk0);
            float v1 = fmaf(s[j][1], 0.125f, mk1);
            float v2 = fmaf(s[j][2], 0.125f, mk0);
            float v3 = fmaf(s[j][3], 0.125f, mk1);
            if (diag) {
                if (cg     > row_in)     v0 = -INFINITY;
                if (cg + 1 > row_in)     v1 = -INFINITY;
                if (cg     > row_in + 8) v2 = -INFINITY;
                if (cg + 1 > row_in + 8) v3 = -INFINITY;
            }
            s[j][0] = v0; s[j][1] = v1; s[j][2] = v2; s[j][3] = v3;
            mx0 = fmaxf(mx0, fmaxf(v0, v1));
            mx1 = fmaxf(mx1, fmaxf(v2, v3));
        }
        mx0 = fmaxf(mx0, __shfl_xor_sync(0xffffffffu, mx0, 1));
        mx0 = fmaxf(mx0, __shfl_xor_sync(0xffffffffu, mx0, 2));
        mx1 = fmaxf(mx1, __shfl_xor_sync(0xffffffffu, mx1, 1));
        mx1 = fmaxf(mx1, __shfl_xor_sync(0xffffffffu, mx1, 2));

        float mn0 = fmaxf(m0, mx0), mn1 = fmaxf(m1, mx1);
        float a0 = __expf(m0 - mn0), a1 = __expf(m1 - mn1);
        float ps0 = 0.f, ps1 = 0.f;
        uint32_t pah[4][4], pal[4][4];
#pragma unroll
        for (int j = 0; j < 8; j++) {
            float p0 = __expf(s[j][0] - mn0);
            float p1 = __expf(s[j][1] - mn0);
            float p2 = __expf(s[j][2] - mn1);
            float p3 = __expf(s[j][3] - mn1);
            ps0 += p0 + p1;
            ps1 += p2 + p3;
            __nv_bfloat16 h0 = __float2bfloat16(p0), h1 = __float2bfloat16(p1);
            __nv_bfloat16 h2 = __float2bfloat16(p2), h3 = __float2bfloat16(p3);
            int t = j >> 1, hf = (j & 1) * 2;
            union { __nv_bfloat16 hh[2]; uint32_t u; } u01, u23;
            u01.hh[0] = h0; u01.hh[1] = h1;
            u23.hh[0] = h2; u23.hh[1] = h3;
            pah[t][hf]     = u01.u;
            pah[t][hf + 1] = u23.u;
            pal[t][hf]     = packbf2(p0 - __bfloat162float(h0), p1 - __bfloat162float(h1));
            pal[t][hf + 1] = packbf2(p2 - __bfloat162float(h2), p3 - __bfloat162float(h3));
        }
        ps0 += __shfl_xor_sync(0xffffffffu, ps0, 1);
        ps0 += __shfl_xor_sync(0xffffffffu, ps0, 2);
        ps1 += __shfl_xor_sync(0xffffffffu, ps1, 1);
        ps1 += __shfl_xor_sync(0xffffffffu, ps1, 2);

        l0 = l0 * a0 + ps0;  l1 = l1 * a1 + ps1;
        m0 = mn0;            m1 = mn1;
#pragma unroll
        for (int j = 0; j < 8; j++) {
            o[j][0] *= a0; o[j][1] *= a0;
            o[j][2] *= a1; o[j][3] *= a1;
        }

        // ---- O += P V (3 hi/lo passes), V via ldmatrix.trans ----
#pragma unroll
        for (int t = 0; t < 4; t++) {
#pragma unroll
            for (int dp = 0; dp < 4; dp++) {
                uint32_t vh4[4], vl4[4];
                uint32_t vaddr = st + 2 * TILE_KB
                               + (uint32_t)((16 * t + vrow) * ROWB + (vcol + dp * 16) * 2);
                ldm4t(vh4, vaddr);
                ldm4t(vl4, vaddr + TILE_KB);
                mma_bf16(o[2 * dp],     pah[t], vh4);
                mma_bf16(o[2 * dp],     pal[t], vh4);
                mma_bf16(o[2 * dp],     pah[t], vl4);
                mma_bf16(o[2 * dp + 1], pah[t], vh4 + 2);
                mma_bf16(o[2 * dp + 1], pal[t], vh4 + 2);
                mma_bf16(o[2 * dp + 1], pah[t], vl4 + 2);
            }
        }
    }

    // ---- normalize + write [b][t][h*64+d] ----
    float inv0 = 1.f / l0, inv1 = 1.f / l1;
    int qg0 = q0 + row_in;
#pragma unroll
    for (int j = 0; j < 8; j++) {
        int d = 8 * j + c2;
        float* op0 = out + ((size_t)(b * SEQ + qg0)) * HID + h * HD + d;
        float* op1 = out + ((size_t)(b * SEQ + qg0 + 8)) * HID + h * HD + d;
        *(float2*)op0 = make_float2(o[j][0] * inv0, o[j][1] * inv0);
        *(float2*)op1 = make_float2(o[j][2] * inv1, o[j][3] * inv1);
    }
}

// ---------------------------------------------------------------------------
// Launch
// ---------------------------------------------------------------------------
extern "C" void kernel_launch(void* const* d_in, const int* in_sizes, int n_in,
                              void* d_out, int out_size)
{
    (void)in_sizes; (void)n_in; (void)out_size;

    const float* X    = (const float*)d_in[0];
    const float* amsk = (const float*)d_in[1];
    const float* Wq = (const float*)d_in[2];
    const float* bq = (const float*)d_in[3];
    const float* Aq = (const float*)d_in[4];
    const float* Bq = (const float*)d_in[5];
    const float* Wk = (const float*)d_in[6];
    const float* bk = (const float*)d_in[7];
    const float* Ak = (const float*)d_in[8];
    const float* Bk = (const float*)d_in[9];
    const float* Wv = (const float*)d_in[10];
    const float* bv = (const float*)d_in[11];
    const float* Av = (const float*)d_in[12];
    const float* Bv = (const float*)d_in[13];

    // 1) Split X to bf16 hi/lo; fold LoRA into W_eff hi/lo
    xsplit_kernel<<<BATCH * SEQ * HID / (256 * 8), 256>>>(X);
    weff_kernel<<<dim3(HID * HID / 1024, 3), 256>>>(Wq, Aq, Bq, Wk, Ak, Bk, Wv, Av, Bv);

    // 2) QKV projections via mma.sync -> g_Ph/g_Pl in [b][h][t][d] bf16 hi/lo
    cudaFuncSetAttribute(qkv_gemm_mma, cudaFuncAttributeMaxDynamicSharedMemorySize, GEMM_SMEM);
    qkv_gemm_mma<<<dim3(HID / 128, (BATCH * SEQ) / 128, 3), 256, GEMM_SMEM>>>(bq, bk, bv);

    // 3) Causal flash attention via mma.sync -> d_out
    cudaFuncSetAttribute(attn_mma, cudaFuncAttributeMaxDynamicSharedMemorySize, ATTN_SMEM);
    attn_mma<<<dim3(SEQ / 64, BATCH * NH), 128, ATTN_SMEM>>>(amsk, (float*)d_out);
}

// round 7
// speedup vs baseline: 4.4874x; 1.1242x over previous
#include <cuda_runtime.h>
#include <cuda_bf16.h>
#include <math.h>
#include <stdint.h>

// Problem constants
#define BATCH 4
#define SEQ   2048
#define HID   1024
#define NH    16
#define HD    64
#define RANK  8
#define LORA_SCALE 2.0f

// ---------------------------------------------------------------------------
// Device scratch: X and W_eff in bf16 hi/lo; Q/K/V results in bf16 hi/lo
// ---------------------------------------------------------------------------
__device__ __nv_bfloat16 g_Xhi[BATCH * SEQ * HID];
__device__ __nv_bfloat16 g_Xlo[BATCH * SEQ * HID];
__device__ __nv_bfloat16 g_Whi[3][HID * HID];
__device__ __nv_bfloat16 g_Wlo[3][HID * HID];
__device__ __nv_bfloat16 g_Ph[3][BATCH * NH * SEQ * HD];   // [p][b][h][t][d] hi
__device__ __nv_bfloat16 g_Pl[3][BATCH * NH * SEQ * HD];   // lo

// ---------------------------------------------------------------------------
// Helpers
// ---------------------------------------------------------------------------
__device__ __forceinline__ uint32_t smem_u32(const void* p) {
    uint32_t a;
    asm("{ .reg .u64 t; cvta.to.shared.u64 t, %1; cvt.u32.u64 %0, t; }" : "=r"(a) : "l"(p));
    return a;
}
__device__ __forceinline__ void cpa16(uint32_t s, const void* g) {
    asm volatile("cp.async.cg.shared.global [%0], [%1], 16;" :: "r"(s), "l"(g) : "memory");
}
__device__ __forceinline__ void cp_commit() {
    asm volatile("cp.async.commit_group;" ::: "memory");
}
template <int N>
__device__ __forceinline__ void cp_wait() {
    asm volatile("cp.async.wait_group %0;" :: "n"(N) : "memory");
}
__device__ __forceinline__ void ldm4(uint32_t* r, uint32_t addr) {
    asm volatile("ldmatrix.sync.aligned.m8n8.x4.shared.b16 {%0,%1,%2,%3}, [%4];"
                 : "=r"(r[0]), "=r"(r[1]), "=r"(r[2]), "=r"(r[3]) : "r"(addr));
}
__device__ __forceinline__ void ldm4t(uint32_t* r, uint32_t addr) {
    asm volatile("ldmatrix.sync.aligned.m8n8.x4.trans.shared.b16 {%0,%1,%2,%3}, [%4];"
                 : "=r"(r[0]), "=r"(r[1]), "=r"(r[2]), "=r"(r[3]) : "r"(addr));
}
__device__ __forceinline__ void mma_bf16(float* c, const uint32_t* a, const uint32_t* b) {
    asm volatile(
        "mma.sync.aligned.m16n8k16.row.col.f32.bf16.bf16.f32 "
        "{%0,%1,%2,%3}, {%4,%5,%6,%7}, {%8,%9}, {%0,%1,%2,%3};"
        : "+f"(c[0]), "+f"(c[1]), "+f"(c[2]), "+f"(c[3])
        : "r"(a[0]), "r"(a[1]), "r"(a[2]), "r"(a[3]), "r"(b[0]), "r"(b[1]));
}
__device__ __forceinline__ uint32_t packbf2(float x, float y) {
    __nv_bfloat162 t = __floats2bfloat162_rn(x, y);
    return *(uint32_t*)&t;
}

// ---------------------------------------------------------------------------
// Kernel 1a: split X into bf16 hi/lo
// ---------------------------------------------------------------------------
__global__ void xsplit_kernel(const float* __restrict__ X)
{
    int i8 = (blockIdx.x * blockDim.x + threadIdx.x) * 8;
    float4 a = *(const float4*)(X + i8);
    float4 b = *(const float4*)(X + i8 + 4);
    float xs[8] = {a.x, a.y, a.z, a.w, b.x, b.y, b.z, b.w};
    union { __nv_bfloat16 h[8]; uint4 v; } uh, ul;
#pragma unroll
    for (int j = 0; j < 8; j++) {
        __nv_bfloat16 hi = __float2bfloat16(xs[j]);
        uh.h[j] = hi;
        ul.h[j] = __float2bfloat16(xs[j] - __bfloat162float(hi));
    }
    *(uint4*)(g_Xhi + i8) = uh.v;
    *(uint4*)(g_Xlo + i8) = ul.v;
}

// ---------------------------------------------------------------------------
// Kernel 1b: fold LoRA into W_eff and split into bf16 hi/lo
// ---------------------------------------------------------------------------
__global__ void weff_kernel(const float* __restrict__ Wq, const float* __restrict__ Aq, const float* __restrict__ Bq,
                            const float* __restrict__ Wk, const float* __restrict__ Ak, const float* __restrict__ Bk,
                            const float* __restrict__ Wv, const float* __restrict__ Av, const float* __restrict__ Bv)
{
    int p = blockIdx.y;
    const float* W  = (p == 0) ? Wq : (p == 1) ? Wk : Wv;
    const float* A  = (p == 0) ? Aq : (p == 1) ? Ak : Av;
    const float* Bm = (p == 0) ? Bq : (p == 1) ? Bk : Bv;

    int i4 = (blockIdx.x * blockDim.x + threadIdx.x) * 4;
    int o = i4 >> 10;
    int i = i4 & 1023;
    float4 w = *(const float4*)&W[i4];
    float br[RANK];
#pragma unroll
    for (int r = 0; r < RANK; r++) br[r] = Bm[o * RANK + r];
    float vals[4] = {w.x, w.y, w.z, w.w};
#pragma unroll
    for (int j = 0; j < 4; j++) {
        float acc = 0.f;
#pragma unroll
        for (int r = 0; r < RANK; r++) acc += br[r] * A[(r << 10) + i + j];
        vals[j] += LORA_SCALE * acc;
    }
    union { __nv_bfloat16 h[4]; uint2 v; } uh, ul;
#pragma unroll
    for (int j = 0; j < 4; j++) {
        __nv_bfloat16 hi = __float2bfloat16(vals[j]);
        uh.h[j] = hi;
        ul.h[j] = __float2bfloat16(vals[j] - __bfloat162float(hi));
    }
    *(uint2*)(g_Whi[p] + i4) = uh.v;
    *(uint2*)(g_Wlo[p] + i4) = ul.v;
}

// ---------------------------------------------------------------------------
// Kernel 2: QKV projection GEMM via mma.sync (bf16 hi/lo, fp32 accum)
//   Epilogue: add bias, re-split to bf16 hi/lo, scatter to [b][h][t][d]
//   launch_bounds(256,2): cap regs at 128 so 2 CTAs/SM co-reside.
// ---------------------------------------------------------------------------
#define PADK 40
#define TILE_B (128 * PADK * 2)
#define STG_B  (4 * TILE_B)
#define GEMM_SMEM (2 * STG_B)
#define NCHUNK 32

__global__ __launch_bounds__(256, 2)
void qkv_gemm_mma(const float* __restrict__ biasq,
                  const float* __restrict__ biask,
                  const float* __restrict__ biasv)
{
    extern __shared__ char smem[];
    uint32_t sbase = smem_u32(smem);

    int tid  = threadIdx.x;
    int lane = tid & 31;
    int wid  = tid >> 5;
    int warp_m = wid >> 2;
    int warp_n = wid & 3;

    int p  = blockIdx.z;
    const float* bias = (p == 0) ? biasq : (p == 1) ? biask : biasv;
    const __nv_bfloat16* Xhi = g_Xhi;
    const __nv_bfloat16* Xlo = g_Xlo;
    const __nv_bfloat16* Whi = g_Whi[p];
    const __nv_bfloat16* Wlo = g_Wlo[p];
    int m0 = blockIdx.y * 128;
    int n0 = blockIdx.x * 128;

    int row0 = tid >> 2;
    int seg0 = tid & 3;

    auto copy_chunk = [&](int c, int st) {
        int col0 = c * 32 + seg0 * 8;
        uint32_t sb = sbase + st * STG_B + row0 * (PADK * 2) + seg0 * 16;
        const __nv_bfloat16* gx = Xhi + (size_t)(m0 + row0) * HID + col0;
        cpa16(sb,                       gx);
        cpa16(sb + 64 * (PADK * 2),     gx + 64 * HID);
        gx = Xlo + (size_t)(m0 + row0) * HID + col0;
        cpa16(sb + TILE_B,                   gx);
        cpa16(sb + TILE_B + 64 * (PADK * 2), gx + 64 * HID);
        const __nv_bfloat16* gw = Whi + (size_t)(n0 + row0) * HID + col0;
        cpa16(sb + 2 * TILE_B,                   gw);
        cpa16(sb + 2 * TILE_B + 64 * (PADK * 2), gw + 64 * HID);
        gw = Wlo + (size_t)(n0 + row0) * HID + col0;
        cpa16(sb + 3 * TILE_B,                   gw);
        cpa16(sb + 3 * TILE_B + 64 * (PADK * 2), gw + 64 * HID);
    };

    float acc[4][4][4];
#pragma unroll
    for (int mt = 0; mt < 4; mt++)
#pragma unroll
        for (int nt = 0; nt < 4; nt++)
#pragma unroll
            for (int k = 0; k < 4; k++) acc[mt][nt][k] = 0.f;

    int a_row = warp_m * 64 + (lane & 7) + ((lane >> 3) & 1) * 8;
    int a_col = (lane >> 4) * 8;
    int b_row = warp_n * 32 + (lane & 7) + ((lane >> 4) & 1) * 8;
    int b_col = ((lane >> 3) & 1) * 8;

    copy_chunk(0, 0);
    cp_commit();

    for (int c = 0; c < NCHUNK; ++c) {
        if (c + 1 < NCHUNK) {
            copy_chunk(c + 1, (c + 1) & 1);
            cp_commit();
            cp_wait<1>();
        } else {
            cp_wait<0>();
        }
        __syncthreads();

        uint32_t xs_hi = sbase + (uint32_t)(c & 1) * STG_B;
        uint32_t xs_lo = xs_hi + TILE_B;
        uint32_t ws_hi = xs_hi + 2 * TILE_B;
        uint32_t ws_lo = xs_hi + 3 * TILE_B;

#pragma unroll
        for (int ks = 0; ks < 32; ks += 16) {
            uint32_t ah[16], al[16], bh[8], bl[8];
#pragma unroll
            for (int mt = 0; mt < 4; mt++) {
                uint32_t off = (uint32_t)(((a_row + mt * 16) * PADK + a_col + ks) * 2);
                ldm4(ah + 4 * mt, xs_hi + off);
                ldm4(al + 4 * mt, xs_lo + off);
            }
#pragma unroll
            for (int np = 0; np < 2; np++) {
                uint32_t off = (uint32_t)(((b_row + np * 16) * PADK + b_col + ks) * 2);
                ldm4(bh + 4 * np, ws_hi + off);
                ldm4(bl + 4 * np, ws_lo + off);
            }
#pragma unroll
            for (int mt = 0; mt < 4; mt++) {
#pragma unroll
                for (int nt = 0; nt < 4; nt++) {
                    const uint32_t* bp_hi = bh + 4 * (nt >> 1) + 2 * (nt & 1);
                    const uint32_t* bp_lo = bl + 4 * (nt >> 1) + 2 * (nt & 1);
                    mma_bf16(acc[mt][nt], ah + 4 * mt, bp_hi);
                    mma_bf16(acc[mt][nt], ah + 4 * mt, bp_lo);
                    mma_bf16(acc[mt][nt], al + 4 * mt, bp_hi);
                }
            }
        }
        __syncthreads();
    }

    // Epilogue: add bias, split to bf16 hi/lo, scatter to [b][h][t][d]
    __nv_bfloat16* oh = g_Ph[p];
    __nv_bfloat16* ol = g_Pl[p];
#pragma unroll
    for (int mt = 0; mt < 4; mt++) {
        int mrow = m0 + warp_m * 64 + mt * 16 + (lane >> 2);
#pragma unroll
        for (int nt = 0; nt < 4; nt++) {
            int o = n0 + warp_n * 32 + nt * 8 + (lane & 3) * 2;
            int h = o >> 6;
            int d = o & 63;
            float b0 = __ldg(&bias[o]);
            float b1 = __ldg(&bias[o + 1]);
#pragma unroll
            for (int half = 0; half < 2; half++) {
                int m = mrow + half * 8;
                int b = m >> 11;
                int t = m & 2047;
                size_t idx = ((size_t)((b * NH + h) * SEQ + t)) * HD + d;
                float v0 = acc[mt][nt][half * 2] + b0;
                float v1 = acc[mt][nt][half * 2 + 1] + b1;
                __nv_bfloat16 h0 = __float2bfloat16(v0);
                __nv_bfloat16 h1 = __float2bfloat16(v1);
                float l0 = v0 - __bfloat162float(h0);
                float l1 = v1 - __bfloat162float(h1);
                union { __nv_bfloat16 h[2]; uint32_t u; } ph, pl;
                ph.h[0] = h0; ph.h[1] = h1;
                pl.h[0] = __float2bfloat16(l0); pl.h[1] = __float2bfloat16(l1);
                *(uint32_t*)(oh + idx) = ph.u;
                *(uint32_t*)(ol + idx) = pl.u;
            }
        }
    }
}

// ---------------------------------------------------------------------------
// Kernel 3: causal flash attention via mma.sync (bf16 hi/lo, fp32 softmax)
//   Tile 64 q x 64 kv, 4 warps, Q staged through stage-0 K slots then
//   register-resident -> smem = 2 stages only (74,240 B) -> 3 CTAs/SM.
//   qb reversed so heaviest CTAs launch first.
// ---------------------------------------------------------------------------
#define AP 72                       // padded row length in bf16 elems
#define ROWB (AP * 2)               // 144 bytes
#define TILE_KB (64 * ROWB)         // 9216 bytes
#define STAGE_B (4 * TILE_KB + 256) // Kh,Kl,Vh,Vl + mask row
#define ATTN_SMEM (2 * STAGE_B)     // 74240 bytes

__global__ __launch_bounds__(128)
void attn_mma(const float* __restrict__ amask, float* __restrict__ out)
{
    extern __shared__ char sm[];
    uint32_t sb = smem_u32(sm);

    int tid  = threadIdx.x;
    int lane = tid & 31;
    int warp = tid >> 5;

    int qb = gridDim.x - 1 - blockIdx.x;    // heaviest (largest qb) first
    int bh = blockIdx.y;
    int b  = bh >> 4;
    int h  = bh & 15;
    int q0 = qb * 64;

    const __nv_bfloat16* Qh = g_Ph[0] + (size_t)bh * SEQ * HD;
    const __nv_bfloat16* Ql = g_Pl[0] + (size_t)bh * SEQ * HD;
    const __nv_bfloat16* Kh = g_Ph[1] + (size_t)bh * SEQ * HD;
    const __nv_bfloat16* Kl = g_Pl[1] + (size_t)bh * SEQ * HD;
    const __nv_bfloat16* Vh = g_Ph[2] + (size_t)bh * SEQ * HD;
    const __nv_bfloat16* Vl = g_Pl[2] + (size_t)bh * SEQ * HD;

    int crow = tid >> 1;             // 0..63
    int cseg = (tid & 1) * 4;        // 0 or 4 (x4 16B segments)

    // K/V/mask stage copy via cp.async
    auto copy_stage = [&](int kb) {
        int st = kb & 1;
        int k0 = kb * 64;
        uint32_t dst = sb + st * STAGE_B + crow * ROWB + cseg * 16;
        size_t src = (size_t)(k0 + crow) * HD + cseg * 8;
#pragma unroll
        for (int c = 0; c < 4; c++) {
            cpa16(dst + c * 16,               Kh + src + c * 8);
            cpa16(dst + c * 16 + TILE_KB,     Kl + src + c * 8);
            cpa16(dst + c * 16 + 2 * TILE_KB, Vh + src + c * 8);
            cpa16(dst + c * 16 + 3 * TILE_KB, Vl + src + c * 8);
        }
        if (tid < 16)
            cpa16(sb + st * STAGE_B + 4 * TILE_KB + tid * 16,
                  amask + (size_t)b * SEQ + k0 + tid * 4);
    };

    // Stage Q (hi/lo) through the stage-0 Kh/Kl slots, extract fragments,
    // then release the buffer to the K/V pipeline.
    {
        size_t src = (size_t)(q0 + crow) * HD + cseg * 8;
        char* qd = sm + crow * ROWB + cseg * 16;
#pragma unroll
        for (int c = 0; c < 4; c++) {
            *(uint4*)(qd + c * 16)           = *(const uint4*)(Qh + src + c * 8);
            *(uint4*)(qd + c * 16 + TILE_KB) = *(const uint4*)(Ql + src + c * 8);
        }
    }
    __syncthreads();   // Q visible in smem

    uint32_t qfh[4][4], qfl[4][4];
    {
        int arow = warp * 16 + (lane & 15);
        int acol = (lane >> 4) * 8;
        uint32_t qbase = sb + arow * ROWB + acol * 2;
#pragma unroll
        for (int ks = 0; ks < 4; ks++) {
            ldm4(qfh[ks], qbase + ks * 32);
            ldm4(qfl[ks], qbase + TILE_KB + ks * 32);
        }
    }
    __syncthreads();   // all warps done reading Q; buffer reusable

    copy_stage(0);
    cp_commit();

    float o[8][4];
#pragma unroll
    for (int j = 0; j < 8; j++)
#pragma unroll
        for (int k = 0; k < 4; k++) o[j][k] = 0.f;
    float m0 = -INFINITY, m1 = -INFINITY, l0 = 0.f, l1 = 0.f;

    int row_in = warp * 16 + (lane >> 2);   // 0..63 (and +8)
    int c2 = 2 * (lane & 3);

    int krow = (lane & 7) + ((lane >> 4) & 1) * 8;
    int kcol = ((lane >> 3) & 1) * 8;
    int vrow = lane & 15;
    int vcol = (lane >> 4) * 8;

    for (int kb = 0; kb <= qb; kb++) {
        cp_wait<0>();
        __syncthreads();
        if (kb + 1 <= qb) {
            copy_stage(kb + 1);
            cp_commit();
        }

        uint32_t st = sb + (uint32_t)(kb & 1) * STAGE_B;

        // ---- S = Q K^T (3 hi/lo passes) ----
        float s[8][4];
#pragma unroll
        for (int j = 0; j < 8; j++)
#pragma unroll
            for (int k = 0; k < 4; k++) s[j][k] = 0.f;

#pragma unroll
        for (int ks = 0; ks < 4; ks++) {
#pragma unroll
            for (int ng = 0; ng < 4; ng++) {
                uint32_t kh4[4], kl4[4];
                uint32_t kaddr = st + (uint32_t)((16 * ng + krow) * ROWB + (kcol + ks * 16) * 2);
                ldm4(kh4, kaddr);
                ldm4(kl4, kaddr + TILE_KB);
                mma_bf16(s[2 * ng],     qfh[ks], kh4);
                mma_bf16(s[2 * ng],     qfh[ks], kl4);
                mma_bf16(s[2 * ng],     qfl[ks], kh4);
                mma_bf16(s[2 * ng + 1], qfh[ks], kh4 + 2);
                mma_bf16(s[2 * ng + 1], qfh[ks], kl4 + 2);
                mma_bf16(s[2 * ng + 1], qfl[ks], kh4 + 2);
            }
        }

        // ---- softmax (online) ----
        const float* maskrow = (const float*)(sm + (kb & 1) * STAGE_B + 4 * TILE_KB);
        bool diag = (kb == qb);
        float mx0 = -INFINITY, mx1 = -INFINITY;
#pragma unroll
        for (int j = 0; j < 8; j++) {
            int cg = 8 * j + c2;
            float mk0 = maskrow[cg], mk1 = maskrow[cg + 1];
            float v0 = fmaf(s[j][0], 0.125f, mk0);
            float v1 = fmaf(s[j][1], 0.125f, mk1);
            float v2 = fmaf(s[j][2], 0.125f, mk0);
            float v3 = fmaf(s[j][3], 0.125f, mk1);
            if (diag) {
                if (cg     > row_in)     v0 = -INFINITY;
                if (cg + 1 > row_in)     v1 = -INFINITY;
                if (cg     > row_in + 8) v2 = -INFINITY;
                if (cg + 1 > row_in + 8) v3 = -INFINITY;
            }
            s[j][0] = v0; s[j][1] = v1; s[j][2] = v2; s[j][3] = v3;
            mx0 = fmaxf(mx0, fmaxf(v0, v1));
            mx1 = fmaxf(mx1, fmaxf(v2, v3));
        }
        mx0 = fmaxf(mx0, __shfl_xor_sync(0xffffffffu, mx0, 1));
        mx0 = fmaxf(mx0, __shfl_xor_sync(0xffffffffu, mx0, 2));
        mx1 = fmaxf(mx1, __shfl_xor_sync(0xffffffffu, mx1, 1));
        mx1 = fmaxf(mx1, __shfl_xor_sync(0xffffffffu, mx1, 2));

        float mn0 = fmaxf(m0, mx0), mn1 = fmaxf(m1, mx1);
        float a0 = __expf(m0 - mn0), a1 = __expf(m1 - mn1);
        float ps0 = 0.f, ps1 = 0.f;
        uint32_t pah[4][4], pal[4][4];
#pragma unroll
        for (int j = 0; j < 8; j++) {
            float p0 = __expf(s[j][0] - mn0);
            float p1 = __expf(s[j][1] - mn0);
            float p2 = __expf(s[j][2] - mn1);
            float p3 = __expf(s[j][3] - mn1);
            ps0 += p0 + p1;
            ps1 += p2 + p3;
            __nv_bfloat16 h0 = __float2bfloat16(p0), h1 = __float2bfloat16(p1);
            __nv_bfloat16 h2 = __float2bfloat16(p2), h3 = __float2bfloat16(p3);
            int t = j >> 1, hf = (j & 1) * 2;
            union { __nv_bfloat16 hh[2]; uint32_t u; } u01, u23;
            u01.hh[0] = h0; u01.hh[1] = h1;
            u23.hh[0] = h2; u23.hh[1] = h3;
            pah[t][hf]     = u01.u;
            pah[t][hf + 1] = u23.u;
            pal[t][hf]     = packbf2(p0 - __bfloat162float(h0), p1 - __bfloat162float(h1));
            pal[t][hf + 1] = packbf2(p2 - __bfloat162float(h2), p3 - __bfloat162float(h3));
        }
        ps0 += __shfl_xor_sync(0xffffffffu, ps0, 1);
        ps0 += __shfl_xor_sync(0xffffffffu, ps0, 2);
        ps1 += __shfl_xor_sync(0xffffffffu, ps1, 1);
        ps1 += __shfl_xor_sync(0xffffffffu, ps1, 2);

        l0 = l0 * a0 + ps0;  l1 = l1 * a1 + ps1;
        m0 = mn0;            m1 = mn1;
#pragma unroll
        for (int j = 0; j < 8; j++) {
            o[j][0] *= a0; o[j][1] *= a0;
            o[j][2] *= a1; o[j][3] *= a1;
        }

        // ---- O += P V (3 hi/lo passes), V via ldmatrix.trans ----
#pragma unroll
        for (int t = 0; t < 4; t++) {
#pragma unroll
            for (int dp = 0; dp < 4; dp++) {
                uint32_t vh4[4], vl4[4];
                uint32_t vaddr = st + 2 * TILE_KB
                               + (uint32_t)((16 * t + vrow) * ROWB + (vcol + dp * 16) * 2);
                ldm4t(vh4, vaddr);
                ldm4t(vl4, vaddr + TILE_KB);
                mma_bf16(o[2 * dp],     pah[t], vh4);
                mma_bf16(o[2 * dp],     pal[t], vh4);
                mma_bf16(o[2 * dp],     pah[t], vl4);
                mma_bf16(o[2 * dp + 1], pah[t], vh4 + 2);
                mma_bf16(o[2 * dp + 1], pal[t], vh4 + 2);
                mma_bf16(o[2 * dp + 1], pah[t], vl4 + 2);
            }
        }
    }

    // ---- normalize + write [b][t][h*64+d] ----
    float inv0 = 1.f / l0, inv1 = 1.f / l1;
    int qg0 = q0 + row_in;
#pragma unroll
    for (int j = 0; j < 8; j++) {
        int d = 8 * j + c2;
        float* op0 = out + ((size_t)(b * SEQ + qg0)) * HID + h * HD + d;
        float* op1 = out + ((size_t)(b * SEQ + qg0 + 8)) * HID + h * HD + d;
        *(float2*)op0 = make_float2(o[j][0] * inv0, o[j][1] * inv0);
        *(float2*)op1 = make_float2(o[j][2] * inv1, o[j][3] * inv1);
    }
}

// ---------------------------------------------------------------------------
// Launch
// ---------------------------------------------------------------------------
extern "C" void kernel_launch(void* const* d_in, const int* in_sizes, int n_in,
                              void* d_out, int out_size)
{
    (void)in_sizes; (void)n_in; (void)out_size;

    const float* X    = (const float*)d_in[0];
    const float* amsk = (const float*)d_in[1];
    const float* Wq = (const float*)d_in[2];
    const float* bq = (const float*)d_in[3];
    const float* Aq = (const float*)d_in[4];
    const float* Bq = (const float*)d_in[5];
    const float* Wk = (const float*)d_in[6];
    const float* bk = (const float*)d_in[7];
    const float* Ak = (const float*)d_in[8];
    const float* Bk = (const float*)d_in[9];
    const float* Wv = (const float*)d_in[10];
    const float* bv = (const float*)d_in[11];
    const float* Av = (const float*)d_in[12];
    const float* Bv = (const float*)d_in[13];

    // 1) Split X to bf16 hi/lo; fold LoRA into W_eff hi/lo
    xsplit_kernel<<<BATCH * SEQ * HID / (256 * 8), 256>>>(X);
    weff_kernel<<<dim3(HID * HID / 1024, 3), 256>>>(Wq, Aq, Bq, Wk, Ak, Bk, Wv, Av, Bv);

    // 2) QKV projections via mma.sync -> g_Ph/g_Pl in [b][h][t][d] bf16 hi/lo
    cudaFuncSetAttribute(qkv_gemm_mma, cudaFuncAttributeMaxDynamicSharedMemorySize, GEMM_SMEM);
    qkv_gemm_mma<<<dim3(HID / 128, (BATCH * SEQ) / 128, 3), 256, GEMM_SMEM>>>(bq, bk, bv);

    // 3) Causal flash attention via mma.sync -> d_out
    cudaFuncSetAttribute(attn_mma, cudaFuncAttributeMaxDynamicSharedMemorySize, ATTN_SMEM);
    attn_mma<<<dim3(SEQ / 64, BATCH * NH), 128, ATTN_SMEM>>>(amsk, (float*)d_out);
}